// round 3
// baseline (speedup 1.0000x reference)
#include <cuda_runtime.h>
#include <math.h>

// Problem constants
#define B_ 4
#define L_ 2048
#define C_ 1024
#define H_ 16
#define D_ 64
#define M_ (B_ * L_)   // 8192
#define N_ (3 * C_)    // 3072
#define K_ (C_)        // 1024

// Scratch: Q/K/V in [B, H, L, D] layout (each 32 MB)
__device__ float g_q[B_ * H_ * L_ * D_];
__device__ float g_k[B_ * H_ * L_ * D_];
__device__ float g_v[B_ * H_ * L_ * D_];

// ---------------------------------------------------------------------------
// Kernel 1: qkv = x @ Wqkv + bias, scattered into [B,H,L,D] Q/K/V scratch.
// 128x128x16 tile, 256 threads, 8x8 register micro-tile per thread.
// ---------------------------------------------------------------------------
__global__ __launch_bounds__(256) void qkv_gemm_kernel(
    const float* __restrict__ x, const float* __restrict__ W,
    const float* __restrict__ bias)
{
    __shared__ float As[16][128];   // A^T tile: As[k][m]
    __shared__ float Bs[16][128];   // B tile:   Bs[k][n]

    const int tid = threadIdx.x;
    const int m0 = blockIdx.y * 128;
    const int n0 = blockIdx.x * 128;
    const int tm = (tid >> 4) << 3;   // 0..120 step 8
    const int tn = (tid & 15) << 3;   // 0..120 step 8

    float acc[8][8];
#pragma unroll
    for (int i = 0; i < 8; i++)
#pragma unroll
        for (int j = 0; j < 8; j++) acc[i][j] = 0.0f;

    for (int k0 = 0; k0 < K_; k0 += 16) {
#pragma unroll
        for (int it = 0; it < 2; it++) {
            int lin = tid + it * 256;            // 0..511
            // A: 128 rows x 16 cols, float4 along k
            int arow = lin >> 2;                 // 0..127
            int acol = (lin & 3) << 2;           // 0,4,8,12
            float4 a = *reinterpret_cast<const float4*>(
                &x[(m0 + arow) * K_ + k0 + acol]);
            As[acol + 0][arow] = a.x;
            As[acol + 1][arow] = a.y;
            As[acol + 2][arow] = a.z;
            As[acol + 3][arow] = a.w;
            // B: 16 rows x 128 cols, float4 along n
            int brow = lin >> 5;                 // 0..15
            int bcol = (lin & 31) << 2;          // 0..124
            *reinterpret_cast<float4*>(&Bs[brow][bcol]) =
                *reinterpret_cast<const float4*>(&W[(k0 + brow) * N_ + n0 + bcol]);
        }
        __syncthreads();

#pragma unroll
        for (int kk = 0; kk < 16; kk++) {
            float a[8], b[8];
            *reinterpret_cast<float4*>(&a[0]) = *reinterpret_cast<float4*>(&As[kk][tm]);
            *reinterpret_cast<float4*>(&a[4]) = *reinterpret_cast<float4*>(&As[kk][tm + 4]);
            *reinterpret_cast<float4*>(&b[0]) = *reinterpret_cast<float4*>(&Bs[kk][tn]);
            *reinterpret_cast<float4*>(&b[4]) = *reinterpret_cast<float4*>(&Bs[kk][tn + 4]);
#pragma unroll
            for (int i = 0; i < 8; i++)
#pragma unroll
                for (int j = 0; j < 8; j++)
                    acc[i][j] = fmaf(a[i], b[j], acc[i][j]);
        }
        __syncthreads();
    }

    // Epilogue: bias + scatter into [B,H,L,D]. All n in this block share q/k/v.
    const int which = n0 >> 10;  // 0=q, 1=k, 2=v (128 | 1024)
    float* dst = (which == 0) ? g_q : ((which == 1) ? g_k : g_v);
#pragma unroll
    for (int i = 0; i < 8; i++) {
        int m  = m0 + tm + i;
        int bb = m >> 11;            // / L_
        int l  = m & (L_ - 1);
#pragma unroll
        for (int j = 0; j < 8; j++) {
            int n = n0 + tn + j;
            int c = n & (C_ - 1);
            int h = c >> 6;
            int d = c & 63;
            dst[(((bb * H_ + h) * L_ + l) << 6) + d] = acc[i][j] + bias[n];
        }
    }
}

// ---------------------------------------------------------------------------
// Kernel 2: causal flash attention. One block per (b*h, 64-row query tile).
// 64-wide key tiles, online softmax, 4x4 micro-tiles, 256 threads.
// ---------------------------------------------------------------------------
#define SMPAD 65

__global__ __launch_bounds__(256) void attn_kernel(float* __restrict__ y)
{
    extern __shared__ float sm[];
    float* Qt   = sm;                    // [d][i]  64 x 65
    float* Kt   = Qt + 64 * SMPAD;       // [d][j]  64 x 65
    float* Vs   = Kt + 64 * SMPAD;       // [j][d]  64 x 65
    float* Ss   = Vs + 64 * SMPAD;       // [j][i]  64 x 65 (scores, then P)
    float* m_sh = Ss + 64 * SMPAD;       // [64] row max
    float* l_sh = m_sh + 64;             // [64] row sum
    float* al_sh = l_sh + 64;            // [64] rescale factor

    const int bh  = blockIdx.y;          // 0..63  (b*H + h)
    const int qt  = blockIdx.x;          // 0..31  query tile
    const int tid = threadIdx.x;
    const float scale = 0.125f;          // 1/sqrt(64)

    const float* qg = g_q + (bh * L_ + qt * 64) * 64;
    const float* kg = g_k + bh * L_ * 64;
    const float* vg = g_v + bh * L_ * 64;

    // Load Q tile transposed (d-major)
    for (int idx = tid; idx < 4096; idx += 256) {
        int r = idx >> 6, d = idx & 63;
        Qt[d * SMPAD + r] = qg[idx];
    }
    if (tid < 64) { m_sh[tid] = -1e30f; l_sh[tid] = 0.0f; }

    const int ti = (tid >> 4) << 2;      // query rows  [ti, ti+4)
    const int tj = (tid & 15) << 2;      // key cols / d cols [tj, tj+4)

    float O[4][4];
#pragma unroll
    for (int i = 0; i < 4; i++)
#pragma unroll
        for (int j = 0; j < 4; j++) O[i][j] = 0.0f;

    for (int kt = 0; kt <= qt; kt++) {
        __syncthreads();   // protect Kt/Vs/Ss from previous iteration's readers
        for (int idx = tid; idx < 4096; idx += 256) {
            int r = idx >> 6, d = idx & 63;
            float kv = kg[kt * 4096 + idx];
            Kt[d * SMPAD + r] = kv;
            Vs[r * SMPAD + d] = vg[kt * 4096 + idx];
        }
        __syncthreads();

        // S = Q K^T (4x4 micro-tile per thread)
        float S[4][4];
#pragma unroll
        for (int i = 0; i < 4; i++)
#pragma unroll
            for (int j = 0; j < 4; j++) S[i][j] = 0.0f;

#pragma unroll 8
        for (int d = 0; d < 64; d++) {
            float a0 = Qt[d * SMPAD + ti + 0];
            float a1 = Qt[d * SMPAD + ti + 1];
            float a2 = Qt[d * SMPAD + ti + 2];
            float a3 = Qt[d * SMPAD + ti + 3];
            float b0 = Kt[d * SMPAD + tj + 0];
            float b1 = Kt[d * SMPAD + tj + 1];
            float b2 = Kt[d * SMPAD + tj + 2];
            float b3 = Kt[d * SMPAD + tj + 3];
            S[0][0] = fmaf(a0, b0, S[0][0]); S[0][1] = fmaf(a0, b1, S[0][1]);
            S[0][2] = fmaf(a0, b2, S[0][2]); S[0][3] = fmaf(a0, b3, S[0][3]);
            S[1][0] = fmaf(a1, b0, S[1][0]); S[1][1] = fmaf(a1, b1, S[1][1]);
            S[1][2] = fmaf(a1, b2, S[1][2]); S[1][3] = fmaf(a1, b3, S[1][3]);
            S[2][0] = fmaf(a2, b0, S[2][0]); S[2][1] = fmaf(a2, b1, S[2][1]);
            S[2][2] = fmaf(a2, b2, S[2][2]); S[2][3] = fmaf(a2, b3, S[2][3]);
            S[3][0] = fmaf(a3, b0, S[3][0]); S[3][1] = fmaf(a3, b1, S[3][1]);
            S[3][2] = fmaf(a3, b2, S[3][2]); S[3][3] = fmaf(a3, b3, S[3][3]);
        }

        // scale + causal mask, write transposed into Ss[j][i]
#pragma unroll
        for (int jj = 0; jj < 4; jj++)
#pragma unroll
            for (int ii = 0; ii < 4; ii++) {
                float s = S[ii][jj] * scale;
                if (kt * 64 + tj + jj > qt * 64 + ti + ii) s = -1e30f;
                Ss[(tj + jj) * SMPAD + ti + ii] = s;
            }
        __syncthreads();

        // Online softmax row update (one thread per row)
        if (tid < 64) {
            float mold = m_sh[tid];
            float mx = mold;
#pragma unroll 8
            for (int j = 0; j < 64; j++) mx = fmaxf(mx, Ss[j * SMPAD + tid]);
            float sum = 0.0f;
#pragma unroll 8
            for (int j = 0; j < 64; j++) {
                float p = __expf(Ss[j * SMPAD + tid] - mx);
                Ss[j * SMPAD + tid] = p;
                sum += p;
            }
            float alpha = __expf(mold - mx);
            m_sh[tid]  = mx;
            l_sh[tid]  = l_sh[tid] * alpha + sum;
            al_sh[tid] = alpha;
        }
        __syncthreads();

        // Rescale O, then O += P @ V (rows ti.., d-cols tj..)
        float a0 = al_sh[ti + 0], a1 = al_sh[ti + 1];
        float a2 = al_sh[ti + 2], a3 = al_sh[ti + 3];
#pragma unroll
        for (int dd = 0; dd < 4; dd++) {
            O[0][dd] *= a0; O[1][dd] *= a1; O[2][dd] *= a2; O[3][dd] *= a3;
        }
#pragma unroll 8
        for (int j = 0; j < 64; j++) {
            float p0 = Ss[j * SMPAD + ti + 0];
            float p1 = Ss[j * SMPAD + ti + 1];
            float p2 = Ss[j * SMPAD + ti + 2];
            float p3 = Ss[j * SMPAD + ti + 3];
            float v0 = Vs[j * SMPAD + tj + 0];
            float v1 = Vs[j * SMPAD + tj + 1];
            float v2 = Vs[j * SMPAD + tj + 2];
            float v3 = Vs[j * SMPAD + tj + 3];
            O[0][0] = fmaf(p0, v0, O[0][0]); O[0][1] = fmaf(p0, v1, O[0][1]);
            O[0][2] = fmaf(p0, v2, O[0][2]); O[0][3] = fmaf(p0, v3, O[0][3]);
            O[1][0] = fmaf(p1, v0, O[1][0]); O[1][1] = fmaf(p1, v1, O[1][1]);
            O[1][2] = fmaf(p1, v2, O[1][2]); O[1][3] = fmaf(p1, v3, O[1][3]);
            O[2][0] = fmaf(p2, v0, O[2][0]); O[2][1] = fmaf(p2, v1, O[2][1]);
            O[2][2] = fmaf(p2, v2, O[2][2]); O[2][3] = fmaf(p2, v3, O[2][3]);
            O[3][0] = fmaf(p3, v0, O[3][0]); O[3][1] = fmaf(p3, v1, O[3][1]);
            O[3][2] = fmaf(p3, v2, O[3][2]); O[3][3] = fmaf(p3, v3, O[3][3]);
        }
    }

    // Final normalize + write y[b, l, h*64 + d]
    const int bb = bh >> 4;
    const int h  = bh & 15;
#pragma unroll
    for (int ii = 0; ii < 4; ii++) {
        float inv = 1.0f / l_sh[ti + ii];
        int row = qt * 64 + ti + ii;
        float* yo = y + (bb * L_ + row) * C_ + h * 64 + tj;
        yo[0] = O[ii][0] * inv;
        yo[1] = O[ii][1] * inv;
        yo[2] = O[ii][2] * inv;
        yo[3] = O[ii][3] * inv;
    }
}

// ---------------------------------------------------------------------------
extern "C" void kernel_launch(void* const* d_in, const int* in_sizes, int n_in,
                              void* d_out, int out_size)
{
    const float* x    = (const float*)d_in[0];
    const float* W    = (const float*)d_in[1];
    const float* bias = (const float*)d_in[2];
    float* y = (float*)d_out;

    dim3 g1(N_ / 128, M_ / 128);
    qkv_gemm_kernel<<<g1, 256>>>(x, W, bias);

    const size_t smem = (4 * 64 * SMPAD + 192) * sizeof(float);  // ~67 KB
    cudaFuncSetAttribute(attn_kernel,
                         cudaFuncAttributeMaxDynamicSharedMemorySize, (int)smem);
    dim3 g2(L_ / 64, B_ * H_);
    attn_kernel<<<g2, 256, smem>>>(y);
}

// round 5
// speedup vs baseline: 1.5920x; 1.5920x over previous
#include <cuda_runtime.h>
#include <cuda_fp16.h>
#include <cstdint>
#include <math.h>

// Problem constants
#define B_ 4
#define L_ 2048
#define C_ 1024
#define H_ 16
#define D_ 64
#define M_ (B_ * L_)   // 8192
#define N_ (3 * C_)    // 3072
#define K_ (C_)        // 1024

// Scratch
__device__ float  g_q[B_ * H_ * L_ * D_];
__device__ float  g_k[B_ * H_ * L_ * D_];
__device__ float  g_v[B_ * H_ * L_ * D_];
__device__ __half g_xh[M_ * K_];     // x in fp16, row-major [M, K]
__device__ __half g_wt[N_ * K_];     // W^T in fp16, [N, K] K-major

__device__ __forceinline__ uint32_t smem_u32(const void* p) {
    uint32_t a;
    asm("{ .reg .u64 t; cvta.to.shared.u64 t, %1; cvt.u32.u64 %0, t; }"
        : "=r"(a) : "l"(p));
    return a;
}

// ---------------------------------------------------------------------------
// Conversion kernels
// ---------------------------------------------------------------------------
__global__ __launch_bounds__(256) void cvt_x_kernel(const float* __restrict__ x) {
    int i = blockIdx.x * 256 + threadIdx.x;          // 0 .. M*K/4-1
    float4 v = reinterpret_cast<const float4*>(x)[i];
    __half2* o = reinterpret_cast<__half2*>(g_xh);
    o[2 * i + 0] = __floats2half2_rn(v.x, v.y);
    o[2 * i + 1] = __floats2half2_rn(v.z, v.w);
}

__global__ __launch_bounds__(256) void cvt_wt_kernel(const float* __restrict__ W) {
    __shared__ float t[32][33];
    int n0 = blockIdx.x * 32;
    int k0 = blockIdx.y * 32;
    int tx = threadIdx.x & 31;
    int ty = threadIdx.x >> 5;   // 0..7
#pragma unroll
    for (int r = 0; r < 4; r++)
        t[ty + r * 8][tx] = W[(k0 + ty + r * 8) * N_ + n0 + tx];
    __syncthreads();
#pragma unroll
    for (int r = 0; r < 4; r++)
        g_wt[(n0 + ty + r * 8) * K_ + k0 + tx] = __float2half_rn(t[tx][ty + r * 8]);
}

// ---------------------------------------------------------------------------
// Kernel 1: QKV GEMM via mma.sync.m16n8k16 (HMMA), fp16 in / fp32 accum.
// CTA tile 128x128, K-tile 32, double-buffered smem, 8 warps (2m x 4n),
// warp tile 64x32. Epilogue: +bias, scatter into [B,H,L,D] q/k/v.
// ---------------------------------------------------------------------------
#define ASTRIDE 40   // halfs per smem row (80B): conflict-free ldmatrix

__global__ __launch_bounds__(256) void qkv_gemm_hmma(const float* __restrict__ bias)
{
    __shared__ __align__(16) __half sA[2][128 * ASTRIDE];
    __shared__ __align__(16) __half sB[2][128 * ASTRIDE];

    const int tid  = threadIdx.x;
    const int lane = tid & 31;
    const int warp = tid >> 5;
    const int m0 = blockIdx.y * 128;
    const int n0 = blockIdx.x * 128;
    const int wm0 = (warp >> 2) * 64;    // warp m offset in tile
    const int wn0 = (warp & 3) * 32;     // warp n offset in tile

    // ldmatrix lane-address components
    const int a_mat  = lane >> 3;
    const int a_row  = ((a_mat & 1) << 3) + (lane & 7);   // row within 16
    const int a_kblk = (a_mat >> 1) << 3;                 // 0 or 8 halfs
    const int b_row  = lane & 7;                          // n within 8
    const int b_koff = ((lane >> 3) & 1) << 3;            // 0 or 8 halfs

    float acc[4][4][4];
#pragma unroll
    for (int i = 0; i < 4; i++)
#pragma unroll
        for (int j = 0; j < 4; j++)
#pragma unroll
            for (int r = 0; r < 4; r++) acc[i][j][r] = 0.0f;

    const uint32_t aS[2] = { smem_u32(sA[0]), smem_u32(sA[1]) };
    const uint32_t bS[2] = { smem_u32(sB[0]), smem_u32(sB[1]) };

    // tile loader: 128 rows x 32 halfs each for A and B (4 x 16B chunks/row)
    auto load_tile = [&](int buf, int t) {
        const int k0 = t * 32;
#pragma unroll
        for (int u = 0; u < 2; u++) {
            int idx = tid + u * 256;          // 0..511
            int row = idx >> 2;
            int ch  = idx & 3;
            uint4 va = *reinterpret_cast<const uint4*>(
                &g_xh[(m0 + row) * K_ + k0 + ch * 8]);
            *reinterpret_cast<uint4*>(&sA[buf][row * ASTRIDE + ch * 8]) = va;
            uint4 vb = *reinterpret_cast<const uint4*>(
                &g_wt[(n0 + row) * K_ + k0 + ch * 8]);
            *reinterpret_cast<uint4*>(&sB[buf][row * ASTRIDE + ch * 8]) = vb;
        }
    };

    load_tile(0, 0);
    __syncthreads();

    int buf = 0;
    for (int t = 0; t < 32; t++) {
        if (t < 31) load_tile(buf ^ 1, t + 1);

#pragma unroll
        for (int ks = 0; ks < 2; ks++) {
            uint32_t a[4][4], b[4][2];
#pragma unroll
            for (int i = 0; i < 4; i++) {
                uint32_t addr = aS[buf] + 2 * ((wm0 + i * 16 + a_row) * ASTRIDE
                                               + ks * 16 + a_kblk);
                asm volatile(
                    "ldmatrix.sync.aligned.m8n8.x4.shared.b16 {%0,%1,%2,%3}, [%4];"
                    : "=r"(a[i][0]), "=r"(a[i][1]), "=r"(a[i][2]), "=r"(a[i][3])
                    : "r"(addr));
            }
#pragma unroll
            for (int j = 0; j < 4; j++) {
                uint32_t addr = bS[buf] + 2 * ((wn0 + j * 8 + b_row) * ASTRIDE
                                               + ks * 16 + b_koff);
                asm volatile(
                    "ldmatrix.sync.aligned.m8n8.x2.shared.b16 {%0,%1}, [%2];"
                    : "=r"(b[j][0]), "=r"(b[j][1])
                    : "r"(addr));
            }
#pragma unroll
            for (int i = 0; i < 4; i++)
#pragma unroll
                for (int j = 0; j < 4; j++) {
                    asm volatile(
                        "mma.sync.aligned.m16n8k16.row.col.f32.f16.f16.f32 "
                        "{%0,%1,%2,%3}, {%4,%5,%6,%7}, {%8,%9}, {%0,%1,%2,%3};"
                        : "+f"(acc[i][j][0]), "+f"(acc[i][j][1]),
                          "+f"(acc[i][j][2]), "+f"(acc[i][j][3])
                        : "r"(a[i][0]), "r"(a[i][1]), "r"(a[i][2]), "r"(a[i][3]),
                          "r"(b[j][0]), "r"(b[j][1]));
                }
        }
        __syncthreads();
        buf ^= 1;
    }

    // Epilogue: bias + scatter into [B,H,L,D]. n0 block is entirely q, k, or v.
    const int which = n0 >> 10;               // 0=q, 1=k, 2=v
    float* dst = (which == 0) ? g_q : ((which == 1) ? g_k : g_v);
    const int gid = lane >> 2;                // 0..7
    const int tig = lane & 3;                 // 0..3

#pragma unroll
    for (int i = 0; i < 4; i++) {
        int m_a = m0 + wm0 + i * 16 + gid;
        int m_b = m_a + 8;
#pragma unroll
        for (int j = 0; j < 4; j++) {
            int n = n0 + wn0 + j * 8 + 2 * tig;
            int cc = n & (C_ - 1);
            int h = cc >> 6, d = cc & 63;
            float b0 = bias[n], b1 = bias[n + 1];
            {
                int bb = m_a >> 11, l = m_a & (L_ - 1);
                float2* p = reinterpret_cast<float2*>(
                    &dst[(((bb * H_ + h) * L_ + l) << 6) + d]);
                *p = make_float2(acc[i][j][0] + b0, acc[i][j][1] + b1);
            }
            {
                int bb = m_b >> 11, l = m_b & (L_ - 1);
                float2* p = reinterpret_cast<float2*>(
                    &dst[(((bb * H_ + h) * L_ + l) << 6) + d]);
                *p = make_float2(acc[i][j][2] + b0, acc[i][j][3] + b1);
            }
        }
    }
}

// ---------------------------------------------------------------------------
// Kernel 2: causal flash attention (fp32 scalar path, unchanged).
// ---------------------------------------------------------------------------
#define SMPAD 65

__global__ __launch_bounds__(256) void attn_kernel(float* __restrict__ y)
{
    extern __shared__ float sm[];
    float* Qt   = sm;
    float* Kt   = Qt + 64 * SMPAD;
    float* Vs   = Kt + 64 * SMPAD;
    float* Ss   = Vs + 64 * SMPAD;
    float* m_sh = Ss + 64 * SMPAD;
    float* l_sh = m_sh + 64;
    float* al_sh = l_sh + 64;

    const int bh  = blockIdx.y;
    const int qt  = blockIdx.x;
    const int tid = threadIdx.x;
    const float scale = 0.125f;

    const float* qg = g_q + (bh * L_ + qt * 64) * 64;
    const float* kg = g_k + bh * L_ * 64;
    const float* vg = g_v + bh * L_ * 64;

    for (int idx = tid; idx < 4096; idx += 256) {
        int r = idx >> 6, d = idx & 63;
        Qt[d * SMPAD + r] = qg[idx];
    }
    if (tid < 64) { m_sh[tid] = -1e30f; l_sh[tid] = 0.0f; }

    const int ti = (tid >> 4) << 2;
    const int tj = (tid & 15) << 2;

    float O[4][4];
#pragma unroll
    for (int i = 0; i < 4; i++)
#pragma unroll
        for (int j = 0; j < 4; j++) O[i][j] = 0.0f;

    for (int kt = 0; kt <= qt; kt++) {
        __syncthreads();
        for (int idx = tid; idx < 4096; idx += 256) {
            int r = idx >> 6, d = idx & 63;
            Kt[d * SMPAD + r] = kg[kt * 4096 + idx];
            Vs[r * SMPAD + d] = vg[kt * 4096 + idx];
        }
        __syncthreads();

        float S[4][4];
#pragma unroll
        for (int i = 0; i < 4; i++)
#pragma unroll
            for (int j = 0; j < 4; j++) S[i][j] = 0.0f;

#pragma unroll 8
        for (int d = 0; d < 64; d++) {
            float a0 = Qt[d * SMPAD + ti + 0];
            float a1 = Qt[d * SMPAD + ti + 1];
            float a2 = Qt[d * SMPAD + ti + 2];
            float a3 = Qt[d * SMPAD + ti + 3];
            float b0 = Kt[d * SMPAD + tj + 0];
            float b1 = Kt[d * SMPAD + tj + 1];
            float b2 = Kt[d * SMPAD + tj + 2];
            float b3 = Kt[d * SMPAD + tj + 3];
            S[0][0] = fmaf(a0, b0, S[0][0]); S[0][1] = fmaf(a0, b1, S[0][1]);
            S[0][2] = fmaf(a0, b2, S[0][2]); S[0][3] = fmaf(a0, b3, S[0][3]);
            S[1][0] = fmaf(a1, b0, S[1][0]); S[1][1] = fmaf(a1, b1, S[1][1]);
            S[1][2] = fmaf(a1, b2, S[1][2]); S[1][3] = fmaf(a1, b3, S[1][3]);
            S[2][0] = fmaf(a2, b0, S[2][0]); S[2][1] = fmaf(a2, b1, S[2][1]);
            S[2][2] = fmaf(a2, b2, S[2][2]); S[2][3] = fmaf(a2, b3, S[2][3]);
            S[3][0] = fmaf(a3, b0, S[3][0]); S[3][1] = fmaf(a3, b1, S[3][1]);
            S[3][2] = fmaf(a3, b2, S[3][2]); S[3][3] = fmaf(a3, b3, S[3][3]);
        }

#pragma unroll
        for (int jj = 0; jj < 4; jj++)
#pragma unroll
            for (int ii = 0; ii < 4; ii++) {
                float s = S[ii][jj] * scale;
                if (kt * 64 + tj + jj > qt * 64 + ti + ii) s = -1e30f;
                Ss[(tj + jj) * SMPAD + ti + ii] = s;
            }
        __syncthreads();

        if (tid < 64) {
            float mold = m_sh[tid];
            float mx = mold;
#pragma unroll 8
            for (int j = 0; j < 64; j++) mx = fmaxf(mx, Ss[j * SMPAD + tid]);
            float sum = 0.0f;
#pragma unroll 8
            for (int j = 0; j < 64; j++) {
                float p = __expf(Ss[j * SMPAD + tid] - mx);
                Ss[j * SMPAD + tid] = p;
                sum += p;
            }
            float alpha = __expf(mold - mx);
            m_sh[tid]  = mx;
            l_sh[tid]  = l_sh[tid] * alpha + sum;
            al_sh[tid] = alpha;
        }
        __syncthreads();

        float a0 = al_sh[ti + 0], a1 = al_sh[ti + 1];
        float a2 = al_sh[ti + 2], a3 = al_sh[ti + 3];
#pragma unroll
        for (int dd = 0; dd < 4; dd++) {
            O[0][dd] *= a0; O[1][dd] *= a1; O[2][dd] *= a2; O[3][dd] *= a3;
        }
#pragma unroll 8
        for (int j = 0; j < 64; j++) {
            float p0 = Ss[j * SMPAD + ti + 0];
            float p1 = Ss[j * SMPAD + ti + 1];
            float p2 = Ss[j * SMPAD + ti + 2];
            float p3 = Ss[j * SMPAD + ti + 3];
            float v0 = Vs[j * SMPAD + tj + 0];
            float v1 = Vs[j * SMPAD + tj + 1];
            float v2 = Vs[j * SMPAD + tj + 2];
            float v3 = Vs[j * SMPAD + tj + 3];
            O[0][0] = fmaf(p0, v0, O[0][0]); O[0][1] = fmaf(p0, v1, O[0][1]);
            O[0][2] = fmaf(p0, v2, O[0][2]); O[0][3] = fmaf(p0, v3, O[0][3]);
            O[1][0] = fmaf(p1, v0, O[1][0]); O[1][1] = fmaf(p1, v1, O[1][1]);
            O[1][2] = fmaf(p1, v2, O[1][2]); O[1][3] = fmaf(p1, v3, O[1][3]);
            O[2][0] = fmaf(p2, v0, O[2][0]); O[2][1] = fmaf(p2, v1, O[2][1]);
            O[2][2] = fmaf(p2, v2, O[2][2]); O[2][3] = fmaf(p2, v3, O[2][3]);
            O[3][0] = fmaf(p3, v0, O[3][0]); O[3][1] = fmaf(p3, v1, O[3][1]);
            O[3][2] = fmaf(p3, v2, O[3][2]); O[3][3] = fmaf(p3, v3, O[3][3]);
        }
    }

    const int bb = bh >> 4;
    const int h  = bh & 15;
#pragma unroll
    for (int ii = 0; ii < 4; ii++) {
        float inv = 1.0f / l_sh[ti + ii];
        int row = qt * 64 + ti + ii;
        float* yo = y + (bb * L_ + row) * C_ + h * 64 + tj;
        yo[0] = O[ii][0] * inv;
        yo[1] = O[ii][1] * inv;
        yo[2] = O[ii][2] * inv;
        yo[3] = O[ii][3] * inv;
    }
}

// ---------------------------------------------------------------------------
extern "C" void kernel_launch(void* const* d_in, const int* in_sizes, int n_in,
                              void* d_out, int out_size)
{
    const float* x    = (const float*)d_in[0];
    const float* W    = (const float*)d_in[1];
    const float* bias = (const float*)d_in[2];
    float* y = (float*)d_out;

    // fp32 -> fp16 conversions
    cvt_x_kernel<<<(M_ * K_ / 4) / 256, 256>>>(x);
    dim3 gt(N_ / 32, K_ / 32);
    cvt_wt_kernel<<<gt, 256>>>(W);

    // HMMA QKV GEMM
    dim3 g1(N_ / 128, M_ / 128);
    qkv_gemm_hmma<<<g1, 256>>>(bias);

    // attention
    const size_t smem = (4 * 64 * SMPAD + 192) * sizeof(float);
    cudaFuncSetAttribute(attn_kernel,
                         cudaFuncAttributeMaxDynamicSharedMemorySize, (int)smem);
    dim3 g2(L_ / 64, B_ * H_);
    attn_kernel<<<g2, 256, smem>>>(y);
}

// round 6
// speedup vs baseline: 5.9661x; 3.7476x over previous
#include <cuda_runtime.h>
#include <cuda_fp16.h>
#include <cstdint>
#include <math.h>

// Problem constants
#define B_ 4
#define L_ 2048
#define C_ 1024
#define H_ 16
#define D_ 64
#define M_ (B_ * L_)   // 8192
#define N_ (3 * C_)    // 3072
#define K_ (C_)        // 1024

// Scratch
__device__ __half g_xh[M_ * K_];        // x in fp16, row-major [M, K]
__device__ __half g_wt[N_ * K_];        // W^T in fp16, [N, K] K-major
__device__ __half g_q16[B_ * H_ * L_ * D_];   // Q fp16 [B,H,L,D]
__device__ __half g_k16[B_ * H_ * L_ * D_];   // K fp16, pre-scaled by 0.125
__device__ __half g_v16[B_ * H_ * L_ * D_];   // V fp16

__device__ __forceinline__ uint32_t smem_u32(const void* p) {
    uint32_t a;
    asm("{ .reg .u64 t; cvta.to.shared.u64 t, %1; cvt.u32.u64 %0, t; }"
        : "=r"(a) : "l"(p));
    return a;
}

__device__ __forceinline__ uint32_t packh2(float lo, float hi) {
    uint32_t r;
    asm("cvt.rn.f16x2.f32 %0, %1, %2;" : "=r"(r) : "f"(hi), "f"(lo));
    return r;
}

// ---------------------------------------------------------------------------
// Conversion kernels
// ---------------------------------------------------------------------------
__global__ __launch_bounds__(256) void cvt_x_kernel(const float* __restrict__ x) {
    int i = blockIdx.x * 256 + threadIdx.x;          // 0 .. M*K/4-1
    float4 v = reinterpret_cast<const float4*>(x)[i];
    __half2* o = reinterpret_cast<__half2*>(g_xh);
    o[2 * i + 0] = __floats2half2_rn(v.x, v.y);
    o[2 * i + 1] = __floats2half2_rn(v.z, v.w);
}

__global__ __launch_bounds__(256) void cvt_wt_kernel(const float* __restrict__ W) {
    __shared__ float t[32][33];
    int n0 = blockIdx.x * 32;
    int k0 = blockIdx.y * 32;
    int tx = threadIdx.x & 31;
    int ty = threadIdx.x >> 5;   // 0..7
#pragma unroll
    for (int r = 0; r < 4; r++)
        t[ty + r * 8][tx] = W[(k0 + ty + r * 8) * N_ + n0 + tx];
    __syncthreads();
#pragma unroll
    for (int r = 0; r < 4; r++)
        g_wt[(n0 + ty + r * 8) * K_ + k0 + tx] = __float2half_rn(t[tx][ty + r * 8]);
}

// ---------------------------------------------------------------------------
// Kernel 1: QKV GEMM via mma.sync.m16n8k16, fp16 in / fp32 accum.
// Epilogue: +bias, -> fp16, scatter into [B,H,L,D] q/k/v (k scaled by 1/8).
// ---------------------------------------------------------------------------
#define ASTRIDE 40   // halfs per smem row (80B): conflict-free ldmatrix

__global__ __launch_bounds__(256) void qkv_gemm_hmma(const float* __restrict__ bias)
{
    __shared__ __align__(16) __half sA[2][128 * ASTRIDE];
    __shared__ __align__(16) __half sB[2][128 * ASTRIDE];

    const int tid  = threadIdx.x;
    const int lane = tid & 31;
    const int warp = tid >> 5;
    const int m0 = blockIdx.y * 128;
    const int n0 = blockIdx.x * 128;
    const int wm0 = (warp >> 2) * 64;
    const int wn0 = (warp & 3) * 32;

    const int a_mat  = lane >> 3;
    const int a_row  = ((a_mat & 1) << 3) + (lane & 7);
    const int a_kblk = (a_mat >> 1) << 3;
    const int b_row  = lane & 7;
    const int b_koff = ((lane >> 3) & 1) << 3;

    float acc[4][4][4];
#pragma unroll
    for (int i = 0; i < 4; i++)
#pragma unroll
        for (int j = 0; j < 4; j++)
#pragma unroll
            for (int r = 0; r < 4; r++) acc[i][j][r] = 0.0f;

    const uint32_t aS[2] = { smem_u32(sA[0]), smem_u32(sA[1]) };
    const uint32_t bS[2] = { smem_u32(sB[0]), smem_u32(sB[1]) };

    auto load_tile = [&](int buf, int t) {
        const int k0 = t * 32;
#pragma unroll
        for (int u = 0; u < 2; u++) {
            int idx = tid + u * 256;
            int row = idx >> 2;
            int ch  = idx & 3;
            uint4 va = *reinterpret_cast<const uint4*>(
                &g_xh[(m0 + row) * K_ + k0 + ch * 8]);
            *reinterpret_cast<uint4*>(&sA[buf][row * ASTRIDE + ch * 8]) = va;
            uint4 vb = *reinterpret_cast<const uint4*>(
                &g_wt[(n0 + row) * K_ + k0 + ch * 8]);
            *reinterpret_cast<uint4*>(&sB[buf][row * ASTRIDE + ch * 8]) = vb;
        }
    };

    load_tile(0, 0);
    __syncthreads();

    int buf = 0;
    for (int t = 0; t < 32; t++) {
        if (t < 31) load_tile(buf ^ 1, t + 1);

#pragma unroll
        for (int ks = 0; ks < 2; ks++) {
            uint32_t a[4][4], b[4][2];
#pragma unroll
            for (int i = 0; i < 4; i++) {
                uint32_t addr = aS[buf] + 2 * ((wm0 + i * 16 + a_row) * ASTRIDE
                                               + ks * 16 + a_kblk);
                asm volatile(
                    "ldmatrix.sync.aligned.m8n8.x4.shared.b16 {%0,%1,%2,%3}, [%4];"
                    : "=r"(a[i][0]), "=r"(a[i][1]), "=r"(a[i][2]), "=r"(a[i][3])
                    : "r"(addr));
            }
#pragma unroll
            for (int j = 0; j < 4; j++) {
                uint32_t addr = bS[buf] + 2 * ((wn0 + j * 8 + b_row) * ASTRIDE
                                               + ks * 16 + b_koff);
                asm volatile(
                    "ldmatrix.sync.aligned.m8n8.x2.shared.b16 {%0,%1}, [%2];"
                    : "=r"(b[j][0]), "=r"(b[j][1])
                    : "r"(addr));
            }
#pragma unroll
            for (int i = 0; i < 4; i++)
#pragma unroll
                for (int j = 0; j < 4; j++) {
                    asm volatile(
                        "mma.sync.aligned.m16n8k16.row.col.f32.f16.f16.f32 "
                        "{%0,%1,%2,%3}, {%4,%5,%6,%7}, {%8,%9}, {%0,%1,%2,%3};"
                        : "+f"(acc[i][j][0]), "+f"(acc[i][j][1]),
                          "+f"(acc[i][j][2]), "+f"(acc[i][j][3])
                        : "r"(a[i][0]), "r"(a[i][1]), "r"(a[i][2]), "r"(a[i][3]),
                          "r"(b[j][0]), "r"(b[j][1]));
                }
        }
        __syncthreads();
        buf ^= 1;
    }

    // Epilogue: bias, fp16 convert (K scaled by 1/8), scatter into [B,H,L,D].
    const int which = n0 >> 10;               // 0=q, 1=k, 2=v
    __half* dst = (which == 0) ? g_q16 : ((which == 1) ? g_k16 : g_v16);
    const float sc = (which == 1) ? 0.125f : 1.0f;
    const int gid = lane >> 2;
    const int tig = lane & 3;

#pragma unroll
    for (int i = 0; i < 4; i++) {
        int m_a = m0 + wm0 + i * 16 + gid;
        int m_b = m_a + 8;
#pragma unroll
        for (int j = 0; j < 4; j++) {
            int n = n0 + wn0 + j * 8 + 2 * tig;
            int cc = n & (C_ - 1);
            int h = cc >> 6, d = cc & 63;
            float b0 = bias[n], b1 = bias[n + 1];
            {
                int bb = m_a >> 11, l = m_a & (L_ - 1);
                __half2* p = reinterpret_cast<__half2*>(
                    &dst[(((bb * H_ + h) * L_ + l) << 6) + d]);
                *p = __floats2half2_rn((acc[i][j][0] + b0) * sc,
                                       (acc[i][j][1] + b1) * sc);
            }
            {
                int bb = m_b >> 11, l = m_b & (L_ - 1);
                __half2* p = reinterpret_cast<__half2*>(
                    &dst[(((bb * H_ + h) * L_ + l) << 6) + d]);
                *p = __floats2half2_rn((acc[i][j][2] + b0) * sc,
                                       (acc[i][j][3] + b1) * sc);
            }
        }
    }
}

// ---------------------------------------------------------------------------
// Kernel 2: causal flash attention with HMMA.
// Block: 256 threads (8 warps). Q tile 128 rows (16/warp), key tile 64.
// Q frags register-resident; softmax in registers (quad shfl reductions);
// P accumulator frags reused directly as PV A-operand; V via ldmatrix.trans.
// ---------------------------------------------------------------------------
#define QSTR 72   // halfs per smem row (144B): conflict-free ldmatrix

__global__ __launch_bounds__(256) void attn_hmma(float* __restrict__ y)
{
    __shared__ __align__(16) __half sQ[128 * QSTR];
    __shared__ __align__(16) __half sK[64 * QSTR];
    __shared__ __align__(16) __half sV[64 * QSTR];

    const int bh   = blockIdx.y;
    const int qt   = gridDim.x - 1 - blockIdx.x;   // heavy blocks first
    const int tid  = threadIdx.x;
    const int lane = tid & 31;
    const int warp = tid >> 5;
    const int g    = lane >> 2;
    const int t    = lane & 3;

    const __half* qg = g_q16 + (bh * L_ + qt * 128) * 64;
    const __half* kg = g_k16 + bh * L_ * 64;
    const __half* vg = g_v16 + bh * L_ * 64;

    const uint32_t sQb = smem_u32(sQ);
    const uint32_t sKb = smem_u32(sK);
    const uint32_t sVb = smem_u32(sV);

    // Load Q tile: 128 rows x 64 halfs = 1024 x 16B
#pragma unroll
    for (int u = 0; u < 4; u++) {
        int idx = tid + u * 256;
        int row = idx >> 3, ch = idx & 7;
        *reinterpret_cast<uint4*>(&sQ[row * QSTR + ch * 8]) =
            *reinterpret_cast<const uint4*>(&qg[row * 64 + ch * 8]);
    }
    __syncthreads();

    // Q fragments (register-resident for whole kernel)
    uint32_t qf[4][4];
#pragma unroll
    for (int ks = 0; ks < 4; ks++) {
        uint32_t addr = sQb + 2 * ((warp * 16 + (lane & 15)) * QSTR
                                   + ks * 16 + (lane >> 4) * 8);
        asm volatile(
            "ldmatrix.sync.aligned.m8n8.x4.shared.b16 {%0,%1,%2,%3}, [%4];"
            : "=r"(qf[ks][0]), "=r"(qf[ks][1]), "=r"(qf[ks][2]), "=r"(qf[ks][3])
            : "r"(addr));
    }

    float m0r = -1e30f, m1r = -1e30f, l0r = 0.0f, l1r = 0.0f;
    float o[8][4];
#pragma unroll
    for (int nf = 0; nf < 8; nf++)
#pragma unroll
        for (int r = 0; r < 4; r++) o[nf][r] = 0.0f;

    const int row0g = qt * 128 + warp * 16 + g;   // global q row (lane, low)
    const int nkt = 2 * (qt + 1);

    for (int kt = 0; kt < nkt; kt++) {
        __syncthreads();
        // Load K,V tiles: 64 rows x 64 halfs each = 512 x 16B each
#pragma unroll
        for (int u = 0; u < 2; u++) {
            int idx = tid + u * 256;
            int row = idx >> 3, ch = idx & 7;
            *reinterpret_cast<uint4*>(&sK[row * QSTR + ch * 8]) =
                *reinterpret_cast<const uint4*>(&kg[(kt * 64 + row) * 64 + ch * 8]);
            *reinterpret_cast<uint4*>(&sV[row * QSTR + ch * 8]) =
                *reinterpret_cast<const uint4*>(&vg[(kt * 64 + row) * 64 + ch * 8]);
        }
        __syncthreads();

        // S = Q K^T : 8 key-frags x 4 k-steps
        float s[8][4];
#pragma unroll
        for (int nf = 0; nf < 8; nf++)
#pragma unroll
            for (int r = 0; r < 4; r++) s[nf][r] = 0.0f;

#pragma unroll
        for (int ks = 0; ks < 4; ks++) {
#pragma unroll
            for (int nf = 0; nf < 8; nf++) {
                uint32_t b0, b1;
                uint32_t addr = sKb + 2 * ((nf * 8 + (lane & 7)) * QSTR
                                           + ks * 16 + ((lane >> 3) & 1) * 8);
                asm volatile(
                    "ldmatrix.sync.aligned.m8n8.x2.shared.b16 {%0,%1}, [%2];"
                    : "=r"(b0), "=r"(b1) : "r"(addr));
                asm volatile(
                    "mma.sync.aligned.m16n8k16.row.col.f32.f16.f16.f32 "
                    "{%0,%1,%2,%3}, {%4,%5,%6,%7}, {%8,%9}, {%0,%1,%2,%3};"
                    : "+f"(s[nf][0]), "+f"(s[nf][1]), "+f"(s[nf][2]), "+f"(s[nf][3])
                    : "r"(qf[ks][0]), "r"(qf[ks][1]), "r"(qf[ks][2]), "r"(qf[ks][3]),
                      "r"(b0), "r"(b1));
            }
        }

        // Causal mask (warp-uniform condition)
        if (kt * 64 + 63 > qt * 128 + warp * 16) {
#pragma unroll
            for (int nf = 0; nf < 8; nf++) {
                int col = kt * 64 + nf * 8 + 2 * t;
                if (col > row0g)     s[nf][0] = -1e30f;
                if (col + 1 > row0g) s[nf][1] = -1e30f;
                if (col > row0g + 8)     s[nf][2] = -1e30f;
                if (col + 1 > row0g + 8) s[nf][3] = -1e30f;
            }
        }

        // Online softmax: rows g (c0,c1) and g+8 (c2,c3)
        float mx0 = -1e30f, mx1 = -1e30f;
#pragma unroll
        for (int nf = 0; nf < 8; nf++) {
            mx0 = fmaxf(mx0, fmaxf(s[nf][0], s[nf][1]));
            mx1 = fmaxf(mx1, fmaxf(s[nf][2], s[nf][3]));
        }
        mx0 = fmaxf(mx0, __shfl_xor_sync(0xffffffffu, mx0, 1));
        mx0 = fmaxf(mx0, __shfl_xor_sync(0xffffffffu, mx0, 2));
        mx1 = fmaxf(mx1, __shfl_xor_sync(0xffffffffu, mx1, 1));
        mx1 = fmaxf(mx1, __shfl_xor_sync(0xffffffffu, mx1, 2));

        float mn0 = fmaxf(m0r, mx0), mn1 = fmaxf(m1r, mx1);
        float al0 = __expf(m0r - mn0), al1 = __expf(m1r - mn1);
        m0r = mn0; m1r = mn1;

        float sum0 = 0.0f, sum1 = 0.0f;
        uint32_t pf[8][2];
#pragma unroll
        for (int nf = 0; nf < 8; nf++) {
            float p0 = __expf(s[nf][0] - mn0);
            float p1 = __expf(s[nf][1] - mn0);
            float p2 = __expf(s[nf][2] - mn1);
            float p3 = __expf(s[nf][3] - mn1);
            sum0 += p0 + p1;
            sum1 += p2 + p3;
            pf[nf][0] = packh2(p0, p1);
            pf[nf][1] = packh2(p2, p3);
        }
        sum0 += __shfl_xor_sync(0xffffffffu, sum0, 1);
        sum0 += __shfl_xor_sync(0xffffffffu, sum0, 2);
        sum1 += __shfl_xor_sync(0xffffffffu, sum1, 1);
        sum1 += __shfl_xor_sync(0xffffffffu, sum1, 2);
        l0r = l0r * al0 + sum0;
        l1r = l1r * al1 + sum1;

        // Rescale O
#pragma unroll
        for (int nf = 0; nf < 8; nf++) {
            o[nf][0] *= al0; o[nf][1] *= al0;
            o[nf][2] *= al1; o[nf][3] *= al1;
        }

        // O += P V : 4 k-steps (keys) x 8 d-frags; A from P regs, B via trans
#pragma unroll
        for (int ks = 0; ks < 4; ks++) {
            uint32_t A0 = pf[2 * ks][0],     A1 = pf[2 * ks][1];
            uint32_t A2 = pf[2 * ks + 1][0], A3 = pf[2 * ks + 1][1];
#pragma unroll
            for (int nf = 0; nf < 8; nf++) {
                uint32_t b0, b1;
                uint32_t addr = sVb + 2 * ((ks * 16 + (lane & 15)) * QSTR + nf * 8);
                asm volatile(
                    "ldmatrix.sync.aligned.m8n8.x2.trans.shared.b16 {%0,%1}, [%2];"
                    : "=r"(b0), "=r"(b1) : "r"(addr));
                asm volatile(
                    "mma.sync.aligned.m16n8k16.row.col.f32.f16.f16.f32 "
                    "{%0,%1,%2,%3}, {%4,%5,%6,%7}, {%8,%9}, {%0,%1,%2,%3};"
                    : "+f"(o[nf][0]), "+f"(o[nf][1]), "+f"(o[nf][2]), "+f"(o[nf][3])
                    : "r"(A0), "r"(A1), "r"(A2), "r"(A3),
                      "r"(b0), "r"(b1));
            }
        }
    }

    // Epilogue: normalize, write y[b, row, h*64 + d]
    const int bb = bh >> 4;
    const int h  = bh & 15;
    const float inv0 = 1.0f / l0r;
    const float inv1 = 1.0f / l1r;
    float* y0 = y + (bb * L_ + row0g) * C_ + h * 64;
    float* y1 = y0 + 8 * C_;
#pragma unroll
    for (int nf = 0; nf < 8; nf++) {
        int d = nf * 8 + 2 * t;
        *reinterpret_cast<float2*>(y0 + d) =
            make_float2(o[nf][0] * inv0, o[nf][1] * inv0);
        *reinterpret_cast<float2*>(y1 + d) =
            make_float2(o[nf][2] * inv1, o[nf][3] * inv1);
    }
}

// ---------------------------------------------------------------------------
extern "C" void kernel_launch(void* const* d_in, const int* in_sizes, int n_in,
                              void* d_out, int out_size)
{
    const float* x    = (const float*)d_in[0];
    const float* W    = (const float*)d_in[1];
    const float* bias = (const float*)d_in[2];
    float* y = (float*)d_out;

    cvt_x_kernel<<<(M_ * K_ / 4) / 256, 256>>>(x);
    dim3 gt(N_ / 32, K_ / 32);
    cvt_wt_kernel<<<gt, 256>>>(W);

    dim3 g1(N_ / 128, M_ / 128);
    qkv_gemm_hmma<<<g1, 256>>>(bias);

    dim3 g2(L_ / 128, B_ * H_);
    attn_hmma<<<g2, 256>>>(y);
}

// round 7
// speedup vs baseline: 7.7517x; 1.2993x over previous
#include <cuda_runtime.h>
#include <cuda_fp16.h>
#include <cstdint>
#include <math.h>

// Problem constants
#define B_ 4
#define L_ 2048
#define C_ 1024
#define H_ 16
#define D_ 64
#define M_ (B_ * L_)   // 8192
#define N_ (3 * C_)    // 3072
#define K_ (C_)        // 1024

// Scratch
__device__ __half g_xh[M_ * K_];        // x in fp16, row-major [M, K]
__device__ __half g_wt[N_ * K_];        // W^T in fp16, [N, K] K-major
__device__ __half g_q16[B_ * H_ * L_ * D_];   // Q fp16 [B,H,L,D]
__device__ __half g_k16[B_ * H_ * L_ * D_];   // K fp16, pre-scaled by 0.125
__device__ __half g_v16[B_ * H_ * L_ * D_];   // V fp16

__device__ __forceinline__ uint32_t smem_u32(const void* p) {
    uint32_t a;
    asm("{ .reg .u64 t; cvta.to.shared.u64 t, %1; cvt.u32.u64 %0, t; }"
        : "=r"(a) : "l"(p));
    return a;
}

__device__ __forceinline__ uint32_t packh2(float lo, float hi) {
    uint32_t r;
    asm("cvt.rn.f16x2.f32 %0, %1, %2;" : "=r"(r) : "f"(hi), "f"(lo));
    return r;
}

__device__ __forceinline__ void cp_async16(uint32_t dst, const void* src) {
    asm volatile("cp.async.cg.shared.global [%0], [%1], 16;"
                 :: "r"(dst), "l"(src));
}
#define CP_COMMIT() asm volatile("cp.async.commit_group;" ::: "memory")
#define CP_WAIT(n)  asm volatile("cp.async.wait_group %0;" :: "n"(n) : "memory")

// ---------------------------------------------------------------------------
// Conversion kernels
// ---------------------------------------------------------------------------
__global__ __launch_bounds__(256) void cvt_x_kernel(const float* __restrict__ x) {
    int i = blockIdx.x * 256 + threadIdx.x;          // 0 .. M*K/4-1
    float4 v = reinterpret_cast<const float4*>(x)[i];
    __half2* o = reinterpret_cast<__half2*>(g_xh);
    o[2 * i + 0] = __floats2half2_rn(v.x, v.y);
    o[2 * i + 1] = __floats2half2_rn(v.z, v.w);
}

__global__ __launch_bounds__(256) void cvt_wt_kernel(const float* __restrict__ W) {
    __shared__ float t[32][33];
    int n0 = blockIdx.x * 32;
    int k0 = blockIdx.y * 32;
    int tx = threadIdx.x & 31;
    int ty = threadIdx.x >> 5;   // 0..7
#pragma unroll
    for (int r = 0; r < 4; r++)
        t[ty + r * 8][tx] = W[(k0 + ty + r * 8) * N_ + n0 + tx];
    __syncthreads();
#pragma unroll
    for (int r = 0; r < 4; r++)
        g_wt[(n0 + ty + r * 8) * K_ + k0 + tx] = __float2half_rn(t[tx][ty + r * 8]);
}

// ---------------------------------------------------------------------------
// Kernel 1: QKV GEMM via mma.sync.m16n8k16, fp16 in / fp32 accum.
// 128x128 tile, K-tile 32, 3-stage cp.async pipeline, 8 warps (2m x 4n).
// Epilogue: +bias, -> fp16, scatter into [B,H,L,D] q/k/v (k scaled by 1/8).
// ---------------------------------------------------------------------------
#define ASTRIDE 40                         // halfs per smem row (80B)
#define GEMM_ARR_B (128 * ASTRIDE * 2)     // bytes per A or B array: 10240
#define GEMM_STG_B (2 * GEMM_ARR_B)        // bytes per stage: 20480
#define GEMM_SMEM  (3 * GEMM_STG_B)        // 61440

__global__ __launch_bounds__(256) void qkv_gemm_hmma(const float* __restrict__ bias)
{
    extern __shared__ __align__(16) __half dsm[];
    const uint32_t base = smem_u32(dsm);

    const int tid  = threadIdx.x;
    const int lane = tid & 31;
    const int warp = tid >> 5;
    const int m0 = blockIdx.y * 128;
    const int n0 = blockIdx.x * 128;
    const int wm0 = (warp >> 2) * 64;
    const int wn0 = (warp & 3) * 32;

    const int a_mat  = lane >> 3;
    const int a_row  = ((a_mat & 1) << 3) + (lane & 7);
    const int a_kblk = (a_mat >> 1) << 3;
    // x4 B-operand lane addressing (pairs of 8-col frags)
    const int b_row4  = (lane & 7) + ((lane >> 4) << 3);
    const int b_koff4 = ((lane >> 3) & 1) << 3;

    float acc[4][4][4];
#pragma unroll
    for (int i = 0; i < 4; i++)
#pragma unroll
        for (int j = 0; j < 4; j++)
#pragma unroll
            for (int r = 0; r < 4; r++) acc[i][j][r] = 0.0f;

    // load row/chunk for this thread (same for A and B, 2 rows apart)
    const int l_row = tid >> 2;          // 0..63
    const int l_ch  = tid & 3;           // 0..3

    auto load_tile = [&](int s, int t) {
        const int k0 = t * 32;
        const uint32_t sa = base + s * GEMM_STG_B;
        const uint32_t sb = sa + GEMM_ARR_B;
#pragma unroll
        for (int u = 0; u < 2; u++) {
            int row = l_row + u * 64;
            uint32_t off = (uint32_t)(row * ASTRIDE + l_ch * 8) * 2u;
            cp_async16(sa + off, &g_xh[(m0 + row) * K_ + k0 + l_ch * 8]);
            cp_async16(sb + off, &g_wt[(n0 + row) * K_ + k0 + l_ch * 8]);
        }
    };

    load_tile(0, 0); CP_COMMIT();
    load_tile(1, 1); CP_COMMIT();

    for (int t = 0; t < 32; t++) {
        CP_WAIT(1);
        __syncthreads();
        if (t + 2 < 32) { load_tile((t + 2) % 3, t + 2); CP_COMMIT(); }

        const uint32_t sa = base + (t % 3) * GEMM_STG_B;
        const uint32_t sb = sa + GEMM_ARR_B;

#pragma unroll
        for (int ks = 0; ks < 2; ks++) {
            uint32_t a[4][4], b[4][2];
#pragma unroll
            for (int i = 0; i < 4; i++) {
                uint32_t addr = sa + 2 * ((wm0 + i * 16 + a_row) * ASTRIDE
                                          + ks * 16 + a_kblk);
                asm volatile(
                    "ldmatrix.sync.aligned.m8n8.x4.shared.b16 {%0,%1,%2,%3}, [%4];"
                    : "=r"(a[i][0]), "=r"(a[i][1]), "=r"(a[i][2]), "=r"(a[i][3])
                    : "r"(addr));
            }
#pragma unroll
            for (int j2 = 0; j2 < 2; j2++) {
                uint32_t addr = sb + 2 * ((wn0 + j2 * 16 + b_row4) * ASTRIDE
                                          + ks * 16 + b_koff4);
                asm volatile(
                    "ldmatrix.sync.aligned.m8n8.x4.shared.b16 {%0,%1,%2,%3}, [%4];"
                    : "=r"(b[2 * j2][0]), "=r"(b[2 * j2][1]),
                      "=r"(b[2 * j2 + 1][0]), "=r"(b[2 * j2 + 1][1])
                    : "r"(addr));
            }
#pragma unroll
            for (int i = 0; i < 4; i++)
#pragma unroll
                for (int j = 0; j < 4; j++) {
                    asm volatile(
                        "mma.sync.aligned.m16n8k16.row.col.f32.f16.f16.f32 "
                        "{%0,%1,%2,%3}, {%4,%5,%6,%7}, {%8,%9}, {%0,%1,%2,%3};"
                        : "+f"(acc[i][j][0]), "+f"(acc[i][j][1]),
                          "+f"(acc[i][j][2]), "+f"(acc[i][j][3])
                        : "r"(a[i][0]), "r"(a[i][1]), "r"(a[i][2]), "r"(a[i][3]),
                          "r"(b[j][0]), "r"(b[j][1]));
                }
        }
    }

    // Epilogue: bias, fp16 convert (K scaled by 1/8), scatter into [B,H,L,D].
    const int which = n0 >> 10;               // 0=q, 1=k, 2=v
    __half* dst = (which == 0) ? g_q16 : ((which == 1) ? g_k16 : g_v16);
    const float sc = (which == 1) ? 0.125f : 1.0f;
    const int gid = lane >> 2;
    const int tig = lane & 3;

#pragma unroll
    for (int i = 0; i < 4; i++) {
        int m_a = m0 + wm0 + i * 16 + gid;
        int m_b = m_a + 8;
#pragma unroll
        for (int j = 0; j < 4; j++) {
            int n = n0 + wn0 + j * 8 + 2 * tig;
            int cc = n & (C_ - 1);
            int h = cc >> 6, d = cc & 63;
            float b0 = bias[n], b1 = bias[n + 1];
            {
                int bb = m_a >> 11, l = m_a & (L_ - 1);
                __half2* p = reinterpret_cast<__half2*>(
                    &dst[(((bb * H_ + h) * L_ + l) << 6) + d]);
                *p = __floats2half2_rn((acc[i][j][0] + b0) * sc,
                                       (acc[i][j][1] + b1) * sc);
            }
            {
                int bb = m_b >> 11, l = m_b & (L_ - 1);
                __half2* p = reinterpret_cast<__half2*>(
                    &dst[(((bb * H_ + h) * L_ + l) << 6) + d]);
                *p = __floats2half2_rn((acc[i][j][2] + b0) * sc,
                                       (acc[i][j][3] + b1) * sc);
            }
        }
    }
}

// ---------------------------------------------------------------------------
// Kernel 2: causal flash attention with HMMA.
// 256 threads (8 warps), Q tile 128 rows, key tile 64, cp.async double-buffered
// K/V, x4 ldmatrix everywhere, register softmax, P-frag reuse for PV.
// ---------------------------------------------------------------------------
#define QSTR 72                            // halfs per smem row (144B)
#define ATT_Q_B   (128 * QSTR * 2)         // 18432 bytes
#define ATT_KV_B  (64 * QSTR * 2)          // 9216 bytes per stage per array
#define ATT_SMEM  (ATT_Q_B + 4 * ATT_KV_B) // 55296

__global__ __launch_bounds__(256) void attn_hmma(float* __restrict__ y)
{
    extern __shared__ __align__(16) __half asm_[];
    const uint32_t sQb = smem_u32(asm_);

    const int bid  = blockIdx.x;
    const int qt   = 15 - (bid >> 6);      // heavy tiles first, globally
    const int bh   = bid & 63;
    const int tid  = threadIdx.x;
    const int lane = tid & 31;
    const int warp = tid >> 5;
    const int g    = lane >> 2;
    const int t    = lane & 3;

    const __half* qg = g_q16 + (bh * L_ + qt * 128) * 64;
    const __half* kg = g_k16 + bh * L_ * 64;
    const __half* vg = g_v16 + bh * L_ * 64;

    auto sK = [&](int s) { return sQb + ATT_Q_B + s * ATT_KV_B; };
    auto sV = [&](int s) { return sQb + ATT_Q_B + 2 * ATT_KV_B + s * ATT_KV_B; };

    const int l_row = tid >> 3;            // 0..31
    const int l_ch  = tid & 7;             // 0..7

    auto loadKV = [&](int s, int kt) {
#pragma unroll
        for (int u = 0; u < 2; u++) {
            int row = l_row + u * 32;
            uint32_t off = (uint32_t)(row * QSTR + l_ch * 8) * 2u;
            const int gidx = (kt * 64 + row) * 64 + l_ch * 8;
            cp_async16(sK(s) + off, &kg[gidx]);
            cp_async16(sV(s) + off, &vg[gidx]);
        }
    };

    // Issue first KV load, then stage Q while it flies.
    loadKV(0, 0); CP_COMMIT();

#pragma unroll
    for (int u = 0; u < 4; u++) {
        int idx = tid + u * 256;
        int row = idx >> 3, ch = idx & 7;
        *reinterpret_cast<uint4*>(
            reinterpret_cast<char*>(asm_) + (row * QSTR + ch * 8) * 2) =
            *reinterpret_cast<const uint4*>(&qg[row * 64 + ch * 8]);
    }
    __syncthreads();

    // Q fragments (register-resident for whole kernel)
    uint32_t qf[4][4];
#pragma unroll
    for (int ks = 0; ks < 4; ks++) {
        uint32_t addr = sQb + 2 * ((warp * 16 + (lane & 15)) * QSTR
                                   + ks * 16 + (lane >> 4) * 8);
        asm volatile(
            "ldmatrix.sync.aligned.m8n8.x4.shared.b16 {%0,%1,%2,%3}, [%4];"
            : "=r"(qf[ks][0]), "=r"(qf[ks][1]), "=r"(qf[ks][2]), "=r"(qf[ks][3])
            : "r"(addr));
    }

    float m0r = -1e30f, m1r = -1e30f, l0r = 0.0f, l1r = 0.0f;
    float o[8][4];
#pragma unroll
    for (int nf = 0; nf < 8; nf++)
#pragma unroll
        for (int r = 0; r < 4; r++) o[nf][r] = 0.0f;

    const int row0g = qt * 128 + warp * 16 + g;
    const int nkt = 2 * (qt + 1);

    // x4 lane-address components
    const int k_row4  = (lane & 7) + ((lane >> 4) << 3);      // K rows
    const int k_koff4 = ((lane >> 3) & 1) << 3;               // K k-offset
    const int v_row4  = (lane & 7) + (((lane >> 3) & 1) << 3);// V rows
    const int v_col4  = (lane >> 4) << 3;                     // V col offset

    int sb = 0;
    for (int kt = 0; kt < nkt; kt++) {
        CP_WAIT(0);
        __syncthreads();
        if (kt + 1 < nkt) { loadKV(sb ^ 1, kt + 1); CP_COMMIT(); }

        const uint32_t sKb = sK(sb);
        const uint32_t sVb = sV(sb);

        // S = Q K^T : 8 key-frags x 4 k-steps (x4 ldmatrix, frag pairs)
        float s[8][4];
#pragma unroll
        for (int nf = 0; nf < 8; nf++)
#pragma unroll
            for (int r = 0; r < 4; r++) s[nf][r] = 0.0f;

#pragma unroll
        for (int ks = 0; ks < 4; ks++) {
#pragma unroll
            for (int nf2 = 0; nf2 < 4; nf2++) {
                uint32_t b0, b1, b2, b3;
                uint32_t addr = sKb + 2 * ((nf2 * 16 + k_row4) * QSTR
                                           + ks * 16 + k_koff4);
                asm volatile(
                    "ldmatrix.sync.aligned.m8n8.x4.shared.b16 {%0,%1,%2,%3}, [%4];"
                    : "=r"(b0), "=r"(b1), "=r"(b2), "=r"(b3) : "r"(addr));
                asm volatile(
                    "mma.sync.aligned.m16n8k16.row.col.f32.f16.f16.f32 "
                    "{%0,%1,%2,%3}, {%4,%5,%6,%7}, {%8,%9}, {%0,%1,%2,%3};"
                    : "+f"(s[2 * nf2][0]), "+f"(s[2 * nf2][1]),
                      "+f"(s[2 * nf2][2]), "+f"(s[2 * nf2][3])
                    : "r"(qf[ks][0]), "r"(qf[ks][1]), "r"(qf[ks][2]), "r"(qf[ks][3]),
                      "r"(b0), "r"(b1));
                asm volatile(
                    "mma.sync.aligned.m16n8k16.row.col.f32.f16.f16.f32 "
                    "{%0,%1,%2,%3}, {%4,%5,%6,%7}, {%8,%9}, {%0,%1,%2,%3};"
                    : "+f"(s[2 * nf2 + 1][0]), "+f"(s[2 * nf2 + 1][1]),
                      "+f"(s[2 * nf2 + 1][2]), "+f"(s[2 * nf2 + 1][3])
                    : "r"(qf[ks][0]), "r"(qf[ks][1]), "r"(qf[ks][2]), "r"(qf[ks][3]),
                      "r"(b2), "r"(b3));
            }
        }

        // Causal mask (warp-uniform condition)
        if (kt * 64 + 63 > qt * 128 + warp * 16) {
#pragma unroll
            for (int nf = 0; nf < 8; nf++) {
                int col = kt * 64 + nf * 8 + 2 * t;
                if (col > row0g)     s[nf][0] = -1e30f;
                if (col + 1 > row0g) s[nf][1] = -1e30f;
                if (col > row0g + 8)     s[nf][2] = -1e30f;
                if (col + 1 > row0g + 8) s[nf][3] = -1e30f;
            }
        }

        // Online softmax (register, quad shfl)
        float mx0 = -1e30f, mx1 = -1e30f;
#pragma unroll
        for (int nf = 0; nf < 8; nf++) {
            mx0 = fmaxf(mx0, fmaxf(s[nf][0], s[nf][1]));
            mx1 = fmaxf(mx1, fmaxf(s[nf][2], s[nf][3]));
        }
        mx0 = fmaxf(mx0, __shfl_xor_sync(0xffffffffu, mx0, 1));
        mx0 = fmaxf(mx0, __shfl_xor_sync(0xffffffffu, mx0, 2));
        mx1 = fmaxf(mx1, __shfl_xor_sync(0xffffffffu, mx1, 1));
        mx1 = fmaxf(mx1, __shfl_xor_sync(0xffffffffu, mx1, 2));

        float mn0 = fmaxf(m0r, mx0), mn1 = fmaxf(m1r, mx1);
        float al0 = __expf(m0r - mn0), al1 = __expf(m1r - mn1);
        m0r = mn0; m1r = mn1;

        float sum0 = 0.0f, sum1 = 0.0f;
        uint32_t pf[8][2];
#pragma unroll
        for (int nf = 0; nf < 8; nf++) {
            float p0 = __expf(s[nf][0] - mn0);
            float p1 = __expf(s[nf][1] - mn0);
            float p2 = __expf(s[nf][2] - mn1);
            float p3 = __expf(s[nf][3] - mn1);
            sum0 += p0 + p1;
            sum1 += p2 + p3;
            pf[nf][0] = packh2(p0, p1);
            pf[nf][1] = packh2(p2, p3);
        }
        sum0 += __shfl_xor_sync(0xffffffffu, sum0, 1);
        sum0 += __shfl_xor_sync(0xffffffffu, sum0, 2);
        sum1 += __shfl_xor_sync(0xffffffffu, sum1, 1);
        sum1 += __shfl_xor_sync(0xffffffffu, sum1, 2);
        l0r = l0r * al0 + sum0;
        l1r = l1r * al1 + sum1;

#pragma unroll
        for (int nf = 0; nf < 8; nf++) {
            o[nf][0] *= al0; o[nf][1] *= al0;
            o[nf][2] *= al1; o[nf][3] *= al1;
        }

        // O += P V : 4 k-steps x 4 d-frag-pairs (x4 trans ldmatrix)
#pragma unroll
        for (int ks = 0; ks < 4; ks++) {
            uint32_t A0 = pf[2 * ks][0],     A1 = pf[2 * ks][1];
            uint32_t A2 = pf[2 * ks + 1][0], A3 = pf[2 * ks + 1][1];
#pragma unroll
            for (int nf2 = 0; nf2 < 4; nf2++) {
                uint32_t b0, b1, b2, b3;
                uint32_t addr = sVb + 2 * ((ks * 16 + v_row4) * QSTR
                                           + nf2 * 16 + v_col4);
                asm volatile(
                    "ldmatrix.sync.aligned.m8n8.x4.trans.shared.b16 {%0,%1,%2,%3}, [%4];"
                    : "=r"(b0), "=r"(b1), "=r"(b2), "=r"(b3) : "r"(addr));
                asm volatile(
                    "mma.sync.aligned.m16n8k16.row.col.f32.f16.f16.f32 "
                    "{%0,%1,%2,%3}, {%4,%5,%6,%7}, {%8,%9}, {%0,%1,%2,%3};"
                    : "+f"(o[2 * nf2][0]), "+f"(o[2 * nf2][1]),
                      "+f"(o[2 * nf2][2]), "+f"(o[2 * nf2][3])
                    : "r"(A0), "r"(A1), "r"(A2), "r"(A3), "r"(b0), "r"(b1));
                asm volatile(
                    "mma.sync.aligned.m16n8k16.row.col.f32.f16.f16.f32 "
                    "{%0,%1,%2,%3}, {%4,%5,%6,%7}, {%8,%9}, {%0,%1,%2,%3};"
                    : "+f"(o[2 * nf2 + 1][0]), "+f"(o[2 * nf2 + 1][1]),
                      "+f"(o[2 * nf2 + 1][2]), "+f"(o[2 * nf2 + 1][3])
                    : "r"(A0), "r"(A1), "r"(A2), "r"(A3), "r"(b2), "r"(b3));
            }
        }
        sb ^= 1;
    }

    // Epilogue: normalize, write y[b, row, h*64 + d]
    const int bb = bh >> 4;
    const int h  = bh & 15;
    const float inv0 = 1.0f / l0r;
    const float inv1 = 1.0f / l1r;
    float* y0 = y + (bb * L_ + row0g) * C_ + h * 64;
    float* y1 = y0 + 8 * C_;
#pragma unroll
    for (int nf = 0; nf < 8; nf++) {
        int d = nf * 8 + 2 * t;
        *reinterpret_cast<float2*>(y0 + d) =
            make_float2(o[nf][0] * inv0, o[nf][1] * inv0);
        *reinterpret_cast<float2*>(y1 + d) =
            make_float2(o[nf][2] * inv1, o[nf][3] * inv1);
    }
}

// ---------------------------------------------------------------------------
extern "C" void kernel_launch(void* const* d_in, const int* in_sizes, int n_in,
                              void* d_out, int out_size)
{
    const float* x    = (const float*)d_in[0];
    const float* W    = (const float*)d_in[1];
    const float* bias = (const float*)d_in[2];
    float* y = (float*)d_out;

    cvt_x_kernel<<<(M_ * K_ / 4) / 256, 256>>>(x);
    dim3 gt(N_ / 32, K_ / 32);
    cvt_wt_kernel<<<gt, 256>>>(W);

    cudaFuncSetAttribute(qkv_gemm_hmma,
                         cudaFuncAttributeMaxDynamicSharedMemorySize, GEMM_SMEM);
    dim3 g1(N_ / 128, M_ / 128);
    qkv_gemm_hmma<<<g1, 256, GEMM_SMEM>>>(bias);

    cudaFuncSetAttribute(attn_hmma,
                         cudaFuncAttributeMaxDynamicSharedMemorySize, ATT_SMEM);
    attn_hmma<<<(L_ / 128) * B_ * H_, 256, ATT_SMEM>>>(y);
}